// round 14
// baseline (speedup 1.0000x reference)
#include <cuda_runtime.h>
#include <cuda_bf16.h>
#include <cstdint>

#define N_NODES 100000
#define N_EDGES 1600000
#define IN_C    128
#define HID_C   128
#define OUT_C   64

// ---------------- device scratch (no allocation allowed) ----------------
__device__ float g_h1 [(size_t)N_NODES * HID_C];   // X@W1 (raw)
__device__ float g_h  [(size_t)N_NODES * HID_C];   // layer-1 output (post relu)
__device__ float g_h2 [(size_t)N_NODES * OUT_C];   // h@W2 (raw)
__device__ int   g_deg[N_NODES];
__device__ float g_dinv[N_NODES];
__device__ int   g_rowoff[N_NODES + 1];
__device__ int   g_cursor[N_NODES];
__device__ int   g_partial[512];
__device__ int   g_csrsrc[N_EDGES];
__device__ float g_csrw [N_EDGES];                 // dinv[src] per CSR slot

// ---------------- zero deg ----------------
__global__ void zero_deg_kernel(int n) {
    int i = blockIdx.x * blockDim.x + threadIdx.x;
    int stride = gridDim.x * blockDim.x;
    for (int j = i; j < n; j += stride) g_deg[j] = 0;
}

// ---------------- degree histogram ----------------
__global__ void hist_kernel(const int* __restrict__ dst, int E) {
    int i = blockIdx.x * blockDim.x + threadIdx.x;
    if (i < E) atomicAdd(&g_deg[dst[i]], 1);
}

// ---------------- scan part 1 (block sums) + fused dinv ----------------
__global__ void scan1_kernel(int n) {
    __shared__ int sh[256];
    int t = threadIdx.x;
    int i = blockIdx.x * 256 + t;
    int v = (i < n) ? g_deg[i] : 0;
    if (i < n) g_dinv[i] = rsqrtf((float)v + 1.0f);
    sh[t] = v;
    __syncthreads();
    for (int s = 128; s > 0; s >>= 1) {
        if (t < s) sh[t] += sh[t + s];
        __syncthreads();
    }
    if (t == 0) g_partial[blockIdx.x] = sh[0];
}

__global__ void scan2_kernel(int nparts, int total_hint) {
    __shared__ int sh[512];
    int t = threadIdx.x;
    int v = (t < nparts) ? g_partial[t] : 0;
    sh[t] = v;
    __syncthreads();
    for (int off = 1; off < 512; off <<= 1) {
        int add = (t >= off) ? sh[t - off] : 0;
        __syncthreads();
        sh[t] += add;
        __syncthreads();
    }
    if (t < nparts) g_partial[t] = sh[t] - v;
    if (t == 0) g_rowoff[N_NODES] = total_hint;
}

// scan part 3: exclusive row offsets + zero cursor (fused)
__global__ void scan3_kernel(int n) {
    __shared__ int sh[256];
    int t = threadIdx.x;
    int i = blockIdx.x * 256 + t;
    int v = (i < n) ? g_deg[i] : 0;
    sh[t] = v;
    __syncthreads();
    for (int off = 1; off < 256; off <<= 1) {
        int add = (t >= off) ? sh[t - off] : 0;
        __syncthreads();
        sh[t] += add;
        __syncthreads();
    }
    if (i < n) {
        g_rowoff[i] = g_partial[blockIdx.x] + sh[t] - v;
        g_cursor[i] = 0;
    }
}

// ---------------- bucket scatter: build csr src + weight lists ----------------
__global__ void bucket_kernel(const int* __restrict__ src, const int* __restrict__ dst, int E) {
    int e = blockIdx.x * blockDim.x + threadIdx.x;
    if (e >= E) return;
    int s = src[e];
    int d = dst[e];
    int p = atomicAdd(&g_cursor[d], 1);
    int slot = g_rowoff[d] + p;
    g_csrsrc[slot] = s;
    g_csrw[slot]  = __ldg(&g_dinv[s]);
}

// ---------------- tf32 cvt helper ----------------
__device__ __forceinline__ uint32_t f2tf32(float f) {
    uint32_t u;
    asm("cvt.rna.tf32.f32 %0, %1;" : "=r"(u) : "f"(f));
    return u;
}

// ---------------- mma.sync tf32 GEMM: Y[n, NC] = X[n,128] @ W[128,NC] (raw) ----
template <int NC>
__global__ void __launch_bounds__(256, 1)
mma_gemm_kernel(const float* __restrict__ X, const float* __restrict__ W,
                float* __restrict__ Y, int nrows) {
    constexpr int LA = 132;
    constexpr int LB = NC + 4;
    extern __shared__ uint32_t smu[];
    uint32_t* As = smu;                 // 128*LA
    uint32_t* Bs = smu + 128 * LA;      // 128*LB

    int tid = threadIdx.x;
    int row0 = blockIdx.x * 128;

    for (int i = tid; i < 128 * 32; i += 256) {
        int r = i >> 5, c4 = i & 31;
        float4 v = make_float4(0.f, 0.f, 0.f, 0.f);
        if (row0 + r < nrows)
            v = ((const float4*)(X + (size_t)(row0 + r) * 128))[c4];
        uint4 u = make_uint4(f2tf32(v.x), f2tf32(v.y), f2tf32(v.z), f2tf32(v.w));
        *(uint4*)(As + r * LA + c4 * 4) = u;
    }
    for (int i = tid; i < 128 * (NC / 4); i += 256) {
        int k = i / (NC / 4), n4 = i % (NC / 4);
        float4 v = ((const float4*)(W + (size_t)k * NC))[n4];
        uint4 u = make_uint4(f2tf32(v.x), f2tf32(v.y), f2tf32(v.z), f2tf32(v.w));
        *(uint4*)(Bs + k * LB + n4 * 4) = u;
    }
    __syncthreads();

    int wid = tid >> 5, lane = tid & 31;
    int g = lane >> 2, tg = lane & 3;
    int m0 = wid * 16;
    int rowA = row0 + m0 + g;
    int rowB = rowA + 8;

    uint32_t a[16][4];
    const uint32_t* Ar0 = As + (m0 + g) * LA;
    const uint32_t* Ar1 = As + (m0 + g + 8) * LA;
#pragma unroll
    for (int k = 0; k < 16; k++) {
        a[k][0] = Ar0[k * 8 + tg];
        a[k][1] = Ar1[k * 8 + tg];
        a[k][2] = Ar0[k * 8 + tg + 4];
        a[k][3] = Ar1[k * 8 + tg + 4];
    }

    float* ya = Y + (size_t)rowA * NC + 2 * tg;
    float* yb = Y + (size_t)rowB * NC + 2 * tg;

#pragma unroll 2
    for (int nt = 0; nt < NC / 8; nt++) {
        int n0 = nt * 8;
        float c0 = 0.f, c1 = 0.f, c2 = 0.f, c3 = 0.f;
#pragma unroll
        for (int k = 0; k < 16; k++) {
            uint32_t b0 = Bs[(k * 8 + tg) * LB + n0 + g];
            uint32_t b1 = Bs[(k * 8 + tg + 4) * LB + n0 + g];
            asm volatile(
                "mma.sync.aligned.m16n8k8.row.col.f32.tf32.tf32.f32 "
                "{%0,%1,%2,%3}, {%4,%5,%6,%7}, {%8,%9}, {%0,%1,%2,%3};"
                : "+f"(c0), "+f"(c1), "+f"(c2), "+f"(c3)
                : "r"(a[k][0]), "r"(a[k][1]), "r"(a[k][2]), "r"(a[k][3]),
                  "r"(b0), "r"(b1));
        }
        if (rowA < nrows) *(float2*)(ya + n0) = make_float2(c0, c1);
        if (rowB < nrows) *(float2*)(yb + n0) = make_float2(c2, c3);
    }
}

// ---------------- fused aggregate + combine (R8 serial form, streamed weights) ----
// out[node] = act( di*( sum_s H[s]*w[slot] + H[node]*di ) + bias ),  w[slot]=dinv[s]
template <bool RELU>
__global__ void agg128_kernel(const float* __restrict__ H, const float* __restrict__ bias,
                              float* __restrict__ out, int n) {
    int node = (int)((blockIdx.x * (size_t)blockDim.x + threadIdx.x) >> 5);
    int lane = threadIdx.x & 31;
    if (node >= n) return;
    int beg = g_rowoff[node];
    int cnt = g_deg[node];
    float di = g_dinv[node];

    float4 hv = __ldg((const float4*)(H + (size_t)node * 128) + lane);
    float4 acc = make_float4(hv.x * di, hv.y * di, hv.z * di, hv.w * di);  // self * di
    for (int j = 0; j < cnt; j++) {
        int s = __ldg(&g_csrsrc[beg + j]);
        float ds = __ldg(&g_csrw[beg + j]);        // streamed, not dependent on s
        float4 v = __ldg((const float4*)(H + (size_t)s * 128) + lane);
        acc.x += v.x * ds; acc.y += v.y * ds; acc.z += v.z * ds; acc.w += v.w * ds;
    }
    float4 bv = __ldg((const float4*)bias + lane);
    float4 r = make_float4(acc.x * di + bv.x, acc.y * di + bv.y,
                           acc.z * di + bv.z, acc.w * di + bv.w);
    if (RELU) {
        r.x = fmaxf(r.x, 0.f); r.y = fmaxf(r.y, 0.f);
        r.z = fmaxf(r.z, 0.f); r.w = fmaxf(r.w, 0.f);
    }
    ((float4*)(out + (size_t)node * 128))[lane] = r;
}

// C=64: one warp per node, two half-warps process alternating edges (R8 form)
template <bool RELU>
__global__ void agg64_kernel(const float* __restrict__ H, const float* __restrict__ bias,
                             float* __restrict__ out, int n) {
    int node = (int)((blockIdx.x * (size_t)blockDim.x + threadIdx.x) >> 5);
    int lane = threadIdx.x & 31;
    if (node >= n) return;
    int lane16 = lane & 15;
    int grp = lane >> 4;
    int beg = g_rowoff[node];
    int cnt = g_deg[node];
    float di = g_dinv[node];

    float4 acc = make_float4(0.f, 0.f, 0.f, 0.f);
    if (grp == 0) {
        float4 hv = __ldg((const float4*)(H + (size_t)node * 64) + lane16);
        acc = make_float4(hv.x * di, hv.y * di, hv.z * di, hv.w * di);  // self * di
    }
    for (int j = grp; j < cnt; j += 2) {
        int s = __ldg(&g_csrsrc[beg + j]);
        float ds = __ldg(&g_csrw[beg + j]);        // streamed
        float4 v = __ldg((const float4*)(H + (size_t)s * 64) + lane16);
        acc.x += v.x * ds; acc.y += v.y * ds; acc.z += v.z * ds; acc.w += v.w * ds;
    }
    acc.x += __shfl_xor_sync(0xFFFFFFFFu, acc.x, 16);
    acc.y += __shfl_xor_sync(0xFFFFFFFFu, acc.y, 16);
    acc.z += __shfl_xor_sync(0xFFFFFFFFu, acc.z, 16);
    acc.w += __shfl_xor_sync(0xFFFFFFFFu, acc.w, 16);

    if (grp == 0) {
        float4 bv = __ldg((const float4*)bias + lane16);
        float4 r = make_float4(acc.x * di + bv.x, acc.y * di + bv.y,
                               acc.z * di + bv.z, acc.w * di + bv.w);
        if (RELU) {
            r.x = fmaxf(r.x, 0.f); r.y = fmaxf(r.y, 0.f);
            r.z = fmaxf(r.z, 0.f); r.w = fmaxf(r.w, 0.f);
        }
        ((float4*)(out + (size_t)node * 64))[lane16] = r;
    }
}

// ---------------- launch ----------------
extern "C" void kernel_launch(void* const* d_in, const int* in_sizes, int n_in,
                              void* d_out, int out_size) {
    const float* x  = (const float*)d_in[0];
    const int*   ei = (const int*)d_in[1];
    const float* W1 = (const float*)d_in[2];
    const float* b1 = (const float*)d_in[3];
    const float* W2 = (const float*)d_in[4];
    const float* b2 = (const float*)d_in[5];
    float* out = (float*)d_out;

    const int N = N_NODES;
    const int E = N_EDGES;
    const int* src = ei;
    const int* dst = ei + E;

    float* h1; cudaGetSymbolAddress((void**)&h1, g_h1);
    float* h;  cudaGetSymbolAddress((void**)&h,  g_h);
    float* h2; cudaGetSymbolAddress((void**)&h2, g_h2);

    const int SMEM1 = (128 * 132 + 128 * 132) * 4;  // 135168
    const int SMEM2 = (128 * 132 + 128 * 68) * 4;   // 102400
    cudaFuncSetAttribute(mma_gemm_kernel<128>, cudaFuncAttributeMaxDynamicSharedMemorySize, SMEM1);
    cudaFuncSetAttribute(mma_gemm_kernel<64>,  cudaFuncAttributeMaxDynamicSharedMemorySize, SMEM2);

    // persistent side stream + fork/join events (created once; no device mem)
    static cudaStream_t s2 = nullptr;
    static cudaEvent_t evFork = nullptr, evJoin = nullptr;
    if (!s2) {
        cudaStreamCreateWithFlags(&s2, cudaStreamNonBlocking);
        cudaEventCreateWithFlags(&evFork, cudaEventDisableTiming);
        cudaEventCreateWithFlags(&evJoin, cudaEventDisableTiming);
    }

    const int NPARTS = (N + 255) / 256;  // 391
    const int MBLKS  = (N + 127) / 128;  // 782

    // ---- fork: CSR build on s2, GEMM1 on main stream, concurrently ----
    cudaEventRecord(evFork, 0);
    cudaStreamWaitEvent(s2, evFork, 0);

    // CSR chain (depends only on edge_index)
    zero_deg_kernel<<<256, 256, 0, s2>>>(N);
    hist_kernel<<<(E + 255) / 256, 256, 0, s2>>>(dst, E);
    scan1_kernel<<<NPARTS, 256, 0, s2>>>(N);            // also writes dinv
    scan2_kernel<<<1, 512, 0, s2>>>(NPARTS, E);
    scan3_kernel<<<NPARTS, 256, 0, s2>>>(N);            // also zeros cursor
    bucket_kernel<<<(E + 255) / 256, 256, 0, s2>>>(src, dst, E);

    // GEMM1 (depends only on x, W1) on main stream
    mma_gemm_kernel<128><<<MBLKS, 256, SMEM1>>>(x, W1, h1, N);

    // ---- join ----
    cudaEventRecord(evJoin, s2);
    cudaStreamWaitEvent(0, evJoin, 0);

    // --- layer 1 aggregate: h = relu(dinv*(sum h1[s]*w + h1*dinv) + b1) ---
    agg128_kernel<true><<<(N * 32 + 255) / 256, 256>>>(h1, b1, h, N);

    // --- layer 2 ---
    mma_gemm_kernel<64><<<MBLKS, 256, SMEM2>>>(h, W2, h2, N);
    agg64_kernel<false><<<(N * 32 + 255) / 256, 256>>>(h2, b2, out, N);
}

// round 15
// speedup vs baseline: 1.1172x; 1.1172x over previous
#include <cuda_runtime.h>
#include <cuda_bf16.h>
#include <cstdint>

#define N_NODES 100000
#define N_EDGES 1600000
#define IN_C    128
#define HID_C   128
#define OUT_C   64

// ---------------- device scratch (no allocation allowed) ----------------
__device__ float g_hs1[(size_t)N_NODES * HID_C];   // (X@W1) * dinv[row]
__device__ float g_h  [(size_t)N_NODES * HID_C];   // layer-1 output (post relu)
__device__ float g_hs2[(size_t)N_NODES * OUT_C];   // (h@W2) * dinv[row]
__device__ int   g_deg[N_NODES];
__device__ float g_dinv[N_NODES];
__device__ int   g_rowoff[N_NODES + 1];
__device__ int   g_cursor[N_NODES];
__device__ int   g_partial[512];
__device__ int   g_csrsrc[N_EDGES];

// ---------------- zero deg ----------------
__global__ void zero_deg_kernel(int n) {
    int i = blockIdx.x * blockDim.x + threadIdx.x;
    int stride = gridDim.x * blockDim.x;
    for (int j = i; j < n; j += stride) g_deg[j] = 0;
}

// ---------------- degree histogram ----------------
__global__ void hist_kernel(const int* __restrict__ dst, int E) {
    int i = blockIdx.x * blockDim.x + threadIdx.x;
    if (i < E) atomicAdd(&g_deg[dst[i]], 1);
}

// ---------------- scan part 1 (block sums) + fused dinv ----------------
__global__ void scan1_kernel(int n) {
    __shared__ int sh[256];
    int t = threadIdx.x;
    int i = blockIdx.x * 256 + t;
    int v = (i < n) ? g_deg[i] : 0;
    if (i < n) g_dinv[i] = rsqrtf((float)v + 1.0f);
    sh[t] = v;
    __syncthreads();
    for (int s = 128; s > 0; s >>= 1) {
        if (t < s) sh[t] += sh[t + s];
        __syncthreads();
    }
    if (t == 0) g_partial[blockIdx.x] = sh[0];
}

__global__ void scan2_kernel(int nparts, int total_hint) {
    __shared__ int sh[512];
    int t = threadIdx.x;
    int v = (t < nparts) ? g_partial[t] : 0;
    sh[t] = v;
    __syncthreads();
    for (int off = 1; off < 512; off <<= 1) {
        int add = (t >= off) ? sh[t - off] : 0;
        __syncthreads();
        sh[t] += add;
        __syncthreads();
    }
    if (t < nparts) g_partial[t] = sh[t] - v;
    if (t == 0) g_rowoff[N_NODES] = total_hint;
}

// scan part 3: exclusive row offsets + zero cursor (fused)
__global__ void scan3_kernel(int n) {
    __shared__ int sh[256];
    int t = threadIdx.x;
    int i = blockIdx.x * 256 + t;
    int v = (i < n) ? g_deg[i] : 0;
    sh[t] = v;
    __syncthreads();
    for (int off = 1; off < 256; off <<= 1) {
        int add = (t >= off) ? sh[t - off] : 0;
        __syncthreads();
        sh[t] += add;
        __syncthreads();
    }
    if (i < n) {
        g_rowoff[i] = g_partial[blockIdx.x] + sh[t] - v;
        g_cursor[i] = 0;
    }
}

// ---------------- bucket scatter: build csr src list ----------------
__global__ void bucket_kernel(const int* __restrict__ src, const int* __restrict__ dst, int E) {
    int e = blockIdx.x * blockDim.x + threadIdx.x;
    if (e >= E) return;
    int d = dst[e];
    int p = atomicAdd(&g_cursor[d], 1);
    g_csrsrc[g_rowoff[d] + p] = src[e];
}

// ---------------- tf32 cvt helper ----------------
__device__ __forceinline__ uint32_t f2tf32(float f) {
    uint32_t u;
    asm("cvt.rna.tf32.f32 %0, %1;" : "=r"(u) : "f"(f));
    return u;
}

// ---------------- mma.sync tf32 GEMM: Y[n, NC] = (X[n,128] @ W[128,NC]) * dinv[row] ----
template <int NC>
__global__ void __launch_bounds__(256, 1)
mma_gemm_kernel(const float* __restrict__ X, const float* __restrict__ W,
                float* __restrict__ Y, int nrows) {
    constexpr int LA = 132;
    constexpr int LB = NC + 4;
    extern __shared__ uint32_t smu[];
    uint32_t* As = smu;                 // 128*LA
    uint32_t* Bs = smu + 128 * LA;      // 128*LB

    int tid = threadIdx.x;
    int row0 = blockIdx.x * 128;

    for (int i = tid; i < 128 * 32; i += 256) {
        int r = i >> 5, c4 = i & 31;
        float4 v = make_float4(0.f, 0.f, 0.f, 0.f);
        if (row0 + r < nrows)
            v = ((const float4*)(X + (size_t)(row0 + r) * 128))[c4];
        uint4 u = make_uint4(f2tf32(v.x), f2tf32(v.y), f2tf32(v.z), f2tf32(v.w));
        *(uint4*)(As + r * LA + c4 * 4) = u;
    }
    for (int i = tid; i < 128 * (NC / 4); i += 256) {
        int k = i / (NC / 4), n4 = i % (NC / 4);
        float4 v = ((const float4*)(W + (size_t)k * NC))[n4];
        uint4 u = make_uint4(f2tf32(v.x), f2tf32(v.y), f2tf32(v.z), f2tf32(v.w));
        *(uint4*)(Bs + k * LB + n4 * 4) = u;
    }
    __syncthreads();

    int wid = tid >> 5, lane = tid & 31;
    int g = lane >> 2, tg = lane & 3;
    int m0 = wid * 16;
    int rowA = row0 + m0 + g;
    int rowB = rowA + 8;
    float di0 = (rowA < nrows) ? g_dinv[rowA] : 0.f;
    float di1 = (rowB < nrows) ? g_dinv[rowB] : 0.f;

    uint32_t a[16][4];
    const uint32_t* Ar0 = As + (m0 + g) * LA;
    const uint32_t* Ar1 = As + (m0 + g + 8) * LA;
#pragma unroll
    for (int k = 0; k < 16; k++) {
        a[k][0] = Ar0[k * 8 + tg];
        a[k][1] = Ar1[k * 8 + tg];
        a[k][2] = Ar0[k * 8 + tg + 4];
        a[k][3] = Ar1[k * 8 + tg + 4];
    }

    float* ya = Y + (size_t)rowA * NC + 2 * tg;
    float* yb = Y + (size_t)rowB * NC + 2 * tg;

#pragma unroll 2
    for (int nt = 0; nt < NC / 8; nt++) {
        int n0 = nt * 8;
        float c0 = 0.f, c1 = 0.f, c2 = 0.f, c3 = 0.f;
#pragma unroll
        for (int k = 0; k < 16; k++) {
            uint32_t b0 = Bs[(k * 8 + tg) * LB + n0 + g];
            uint32_t b1 = Bs[(k * 8 + tg + 4) * LB + n0 + g];
            asm volatile(
                "mma.sync.aligned.m16n8k8.row.col.f32.tf32.tf32.f32 "
                "{%0,%1,%2,%3}, {%4,%5,%6,%7}, {%8,%9}, {%0,%1,%2,%3};"
                : "+f"(c0), "+f"(c1), "+f"(c2), "+f"(c3)
                : "r"(a[k][0]), "r"(a[k][1]), "r"(a[k][2]), "r"(a[k][3]),
                  "r"(b0), "r"(b1));
        }
        if (rowA < nrows) *(float2*)(ya + n0) = make_float2(c0 * di0, c1 * di0);
        if (rowB < nrows) *(float2*)(yb + n0) = make_float2(c2 * di1, c3 * di1);
    }
}

// ---------------- fused aggregate + combine (pure gather+add edge loop) ----------
// HS pre-scaled by dinv[row]:  out[node] = act( di*(HS[node] + Σ_s HS[s]) + bias )
template <bool RELU>
__global__ void agg128_kernel(const float* __restrict__ HS, const float* __restrict__ bias,
                              float* __restrict__ out, int n) {
    int node = (int)((blockIdx.x * (size_t)blockDim.x + threadIdx.x) >> 5);
    int lane = threadIdx.x & 31;
    if (node >= n) return;
    int beg = g_rowoff[node];
    int cnt = g_deg[node];

    float4 acc = __ldg((const float4*)(HS + (size_t)node * 128) + lane);  // self term
    for (int j = 0; j < cnt; j++) {
        int s = __ldg(&g_csrsrc[beg + j]);
        float4 v = __ldg((const float4*)(HS + (size_t)s * 128) + lane);
        acc.x += v.x; acc.y += v.y; acc.z += v.z; acc.w += v.w;
    }
    float di = g_dinv[node];
    float4 bv = __ldg((const float4*)bias + lane);
    float4 r = make_float4(acc.x * di + bv.x, acc.y * di + bv.y,
                           acc.z * di + bv.z, acc.w * di + bv.w);
    if (RELU) {
        r.x = fmaxf(r.x, 0.f); r.y = fmaxf(r.y, 0.f);
        r.z = fmaxf(r.z, 0.f); r.w = fmaxf(r.w, 0.f);
    }
    ((float4*)(out + (size_t)node * 128))[lane] = r;
}

// C=64: one warp per node, two half-warps process alternating edges
template <bool RELU>
__global__ void agg64_kernel(const float* __restrict__ HS, const float* __restrict__ bias,
                             float* __restrict__ out, int n) {
    int node = (int)((blockIdx.x * (size_t)blockDim.x + threadIdx.x) >> 5);
    int lane = threadIdx.x & 31;
    if (node >= n) return;
    int lane16 = lane & 15;
    int grp = lane >> 4;
    int beg = g_rowoff[node];
    int cnt = g_deg[node];

    float4 acc = make_float4(0.f, 0.f, 0.f, 0.f);
    if (grp == 0)
        acc = __ldg((const float4*)(HS + (size_t)node * 64) + lane16);  // self term
    for (int j = grp; j < cnt; j += 2) {
        int s = __ldg(&g_csrsrc[beg + j]);
        float4 v = __ldg((const float4*)(HS + (size_t)s * 64) + lane16);
        acc.x += v.x; acc.y += v.y; acc.z += v.z; acc.w += v.w;
    }
    acc.x += __shfl_xor_sync(0xFFFFFFFFu, acc.x, 16);
    acc.y += __shfl_xor_sync(0xFFFFFFFFu, acc.y, 16);
    acc.z += __shfl_xor_sync(0xFFFFFFFFu, acc.z, 16);
    acc.w += __shfl_xor_sync(0xFFFFFFFFu, acc.w, 16);

    if (grp == 0) {
        float di = g_dinv[node];
        float4 bv = __ldg((const float4*)bias + lane16);
        float4 r = make_float4(acc.x * di + bv.x, acc.y * di + bv.y,
                               acc.z * di + bv.z, acc.w * di + bv.w);
        if (RELU) {
            r.x = fmaxf(r.x, 0.f); r.y = fmaxf(r.y, 0.f);
            r.z = fmaxf(r.z, 0.f); r.w = fmaxf(r.w, 0.f);
        }
        ((float4*)(out + (size_t)node * 64))[lane16] = r;
    }
}

// ---------------- launch ----------------
extern "C" void kernel_launch(void* const* d_in, const int* in_sizes, int n_in,
                              void* d_out, int out_size) {
    const float* x  = (const float*)d_in[0];
    const int*   ei = (const int*)d_in[1];
    const float* W1 = (const float*)d_in[2];
    const float* b1 = (const float*)d_in[3];
    const float* W2 = (const float*)d_in[4];
    const float* b2 = (const float*)d_in[5];
    float* out = (float*)d_out;

    const int N = N_NODES;
    const int E = N_EDGES;
    const int* src = ei;
    const int* dst = ei + E;

    float* hs1; cudaGetSymbolAddress((void**)&hs1, g_hs1);
    float* h;   cudaGetSymbolAddress((void**)&h,   g_h);
    float* hs2; cudaGetSymbolAddress((void**)&hs2, g_hs2);

    const int SMEM1 = (128 * 132 + 128 * 132) * 4;  // 135168
    const int SMEM2 = (128 * 132 + 128 * 68) * 4;   // 102400
    cudaFuncSetAttribute(mma_gemm_kernel<128>, cudaFuncAttributeMaxDynamicSharedMemorySize, SMEM1);
    cudaFuncSetAttribute(mma_gemm_kernel<64>,  cudaFuncAttributeMaxDynamicSharedMemorySize, SMEM2);

    // persistent side stream + events (created once; no device mem)
    static cudaStream_t s2 = nullptr;
    static cudaEvent_t evFork = nullptr, evDinv = nullptr, evJoin = nullptr;
    if (!s2) {
        cudaStreamCreateWithFlags(&s2, cudaStreamNonBlocking);
        cudaEventCreateWithFlags(&evFork, cudaEventDisableTiming);
        cudaEventCreateWithFlags(&evDinv, cudaEventDisableTiming);
        cudaEventCreateWithFlags(&evJoin, cudaEventDisableTiming);
    }

    const int NPARTS = (N + 255) / 256;  // 391
    const int MBLKS  = (N + 127) / 128;  // 782

    // ---- two-stage fork ----
    cudaEventRecord(evFork, 0);
    cudaStreamWaitEvent(s2, evFork, 0);

    // stage 1 on s2: degrees + dinv (needed by GEMM1 epilogue)
    zero_deg_kernel<<<256, 256, 0, s2>>>(N);
    hist_kernel<<<(E + 255) / 256, 256, 0, s2>>>(dst, E);
    scan1_kernel<<<NPARTS, 256, 0, s2>>>(N);            // writes dinv + block sums
    cudaEventRecord(evDinv, s2);

    // stage 2 on s2: finish CSR (not needed by GEMM1)
    scan2_kernel<<<1, 512, 0, s2>>>(NPARTS, E);
    scan3_kernel<<<NPARTS, 256, 0, s2>>>(N);            // rowoff + cursor=0
    bucket_kernel<<<(E + 255) / 256, 256, 0, s2>>>(src, dst, E);
    cudaEventRecord(evJoin, s2);

    // main stream: GEMM1 (pre-scaled by dinv) overlaps stage 2
    cudaStreamWaitEvent(0, evDinv, 0);
    mma_gemm_kernel<128><<<MBLKS, 256, SMEM1>>>(x, W1, hs1, N);

    // join before aggregation (needs csrsrc)
    cudaStreamWaitEvent(0, evJoin, 0);

    // --- layer 1 aggregate: h = relu(dinv*(hs1[node] + Σ hs1[s]) + b1) ---
    agg128_kernel<true><<<(N * 32 + 255) / 256, 256>>>(hs1, b1, h, N);

    // --- layer 2 ---
    mma_gemm_kernel<64><<<MBLKS, 256, SMEM2>>>(h, W2, hs2, N);
    agg64_kernel<false><<<(N * 32 + 255) / 256, 256>>>(hs2, b2, out, N);
}